// round 10
// baseline (speedup 1.0000x reference)
#include <cuda_runtime.h>
#include <cuda_bf16.h>

// Problem constants
#define BB   256
#define TT   512
#define IND  128
#define HID  100
#define G4   400          // 4*HID
#define MTOT (BB*TT)      // 131072

// ---------------- device scratch (static globals; no runtime alloc) -------------
__device__ float g_WihT[IND * G4];          // [k][g]
__device__ float g_bias[G4];                // bih + bhh
__device__ float g_pre[(MTOT + 2) * G4];    // [m][g] input projection (+2 rows pad)
__device__ float g_hfinal[BB * HID];        // layer-0 final hidden state

// ---------------- f32x2 packed helpers (Blackwell) ------------------------------
__device__ __forceinline__ unsigned long long fma2(unsigned long long a,
                                                   unsigned long long b,
                                                   unsigned long long c) {
    unsigned long long d;
    asm("fma.rn.f32x2 %0, %1, %2, %3;" : "=l"(d) : "l"(a), "l"(b), "l"(c));
    return d;
}
__device__ __forceinline__ unsigned long long pack2(float lo, float hi) {
    unsigned long long d;
    asm("mov.b64 %0, {%1, %2};" : "=l"(d) : "f"(lo), "f"(hi));
    return d;
}
__device__ __forceinline__ float2 unpack2(unsigned long long v) {
    float lo, hi;
    asm("mov.b64 {%0, %1}, %2;" : "=f"(lo), "=f"(hi) : "l"(v));
    return make_float2(lo, hi);
}

// ---------------- hardware tanh activations (sm_75+) -----------------------------
__device__ __forceinline__ float tanh_hw(float x) {
    float y;
    asm("tanh.approx.f32 %0, %1;" : "=f"(y) : "f"(x));
    return y;
}
__device__ __forceinline__ float sig_hw(float x) {
    return fmaf(tanh_hw(0.5f * x), 0.5f, 0.5f);
}

// ---------------- accurate activations (used outside the hot loop) ---------------
__device__ __forceinline__ float tanhf_(float x) {
    float e = __expf(-2.f * fabsf(x));
    float r = __fdividef(1.f - e, 1.f + e);
    return (x >= 0.f) ? r : -r;
}

// ================= K-prep: WihT + fused bias =====================================
__global__ void prep_kernel(const float* __restrict__ Wih,
                            const float* __restrict__ bih,
                            const float* __restrict__ bhh) {
    int idx = blockIdx.x * 256 + threadIdx.x;
    if (idx < G4 * IND) {
        int g = idx / IND, k = idx - g * IND;
        g_WihT[k * G4 + g] = Wih[idx];
    }
    if (idx < G4) g_bias[idx] = bih[idx] + bhh[idx];
}

// ================= K1: pre = x @ WihT + bias  (f32x2 GEMM) =======================
__global__ void __launch_bounds__(416, 2) gemm_pre_kernel(const float* __restrict__ x) {
    __shared__ float xs[64 * 68];    // [k][row]
    __shared__ float ws[64 * 108];   // [k][gate]

    int tid = threadIdx.x;
    int m0 = blockIdx.x * 64;
    int g0 = blockIdx.y * 100;
    int ty = tid & 15;
    int tx = tid >> 4;

    unsigned long long acc[4][2];
#pragma unroll
    for (int r = 0; r < 4; r++) { acc[r][0] = 0ULL; acc[r][1] = 0ULL; }

    for (int kk = 0; kk < IND; kk += 64) {
        __syncthreads();
        for (int idx = tid; idx < 64 * 16; idx += 416) {
            int r = idx >> 4, c4 = idx & 15;
            float4 v = *(const float4*)&x[(m0 + r) * IND + kk + 4 * c4];
            xs[(4 * c4 + 0) * 68 + r] = v.x;
            xs[(4 * c4 + 1) * 68 + r] = v.y;
            xs[(4 * c4 + 2) * 68 + r] = v.z;
            xs[(4 * c4 + 3) * 68 + r] = v.w;
        }
        for (int idx = tid; idx < 64 * 25; idx += 416) {
            int k = idx / 25, g4i = idx - 25 * k;
            float4 v = *(const float4*)&g_WihT[(kk + k) * G4 + g0 + 4 * g4i];
            *(float4*)&ws[k * 108 + 4 * g4i] = v;
        }
        __syncthreads();

        if (tx < 25) {
#pragma unroll 16
            for (int k = 0; k < 64; k++) {
                float4 xv = *(const float4*)&xs[k * 68 + 4 * ty];
                ulonglong2 wv = *(const ulonglong2*)&ws[k * 108 + 4 * tx];
                unsigned long long d0 = pack2(xv.x, xv.x);
                unsigned long long d1 = pack2(xv.y, xv.y);
                unsigned long long d2 = pack2(xv.z, xv.z);
                unsigned long long d3 = pack2(xv.w, xv.w);
                acc[0][0] = fma2(d0, wv.x, acc[0][0]);
                acc[0][1] = fma2(d0, wv.y, acc[0][1]);
                acc[1][0] = fma2(d1, wv.x, acc[1][0]);
                acc[1][1] = fma2(d1, wv.y, acc[1][1]);
                acc[2][0] = fma2(d2, wv.x, acc[2][0]);
                acc[2][1] = fma2(d2, wv.y, acc[2][1]);
                acc[3][0] = fma2(d3, wv.x, acc[3][0]);
                acc[3][1] = fma2(d3, wv.y, acc[3][1]);
            }
        }
    }

    if (tx < 25) {
        float b0 = g_bias[g0 + 4 * tx + 0];
        float b1 = g_bias[g0 + 4 * tx + 1];
        float b2 = g_bias[g0 + 4 * tx + 2];
        float b3 = g_bias[g0 + 4 * tx + 3];
#pragma unroll
        for (int r = 0; r < 4; r++) {
            float2 e0 = unpack2(acc[r][0]);
            float2 e1 = unpack2(acc[r][1]);
            float4 o = make_float4(e0.x + b0, e0.y + b1, e1.x + b2, e1.y + b3);
            *(float4*)&g_pre[(m0 + 4 * ty + r) * G4 + g0 + 4 * tx] = o;
        }
    }
}

// ================= K2: LSTM recurrence — row-pipelined intervals =================
// 128 blocks x 2 batch rows. Thread = (gate q = tid>>1, k-half = tid&1), Whh
// half-row in 26 packed regs. Each step = two intervals:
//   A: matvec+activation for ROW 0  ||  elementwise c/h update for ROW 1
//   B: matvec+activation for ROW 1  ||  elementwise c/h update for ROW 0
// Phase-2 serialization hides behind matvec issue; single-row accumulation keeps
// regs under the 81 cap (no spills). Activations via hardware tanh.approx.f32.
__global__ void __launch_bounds__(800, 1) lstm_kernel(const float* __restrict__ Whh) {
    __shared__ float h_sh[2][112];     // [100..112) stay 0 -> zero-padded k-slice
    __shared__ float gact[2][G4];

    int tid = threadIdx.x;
    int r0 = blockIdx.x * 2;
    int q = tid >> 1;          // gate index 0..399
    int half = tid & 1;        // k-half: [0,52) or [52,104)

    unsigned long long Wp[26];
#pragma unroll
    for (int j = 0; j < 26; j++) {
        int k = half * 52 + 2 * j;
        float lo = (k < HID)     ? Whh[q * HID + k]     : 0.f;
        float hi = (k + 1 < HID) ? Whh[q * HID + k + 1] : 0.f;
        Wp[j] = pack2(lo, hi);
    }
    if (tid < 224) ((float*)h_sh)[tid] = 0.f;
    if (tid < G4) gact[1][tid] = 0.f;   // so A(0)'s row-1 update yields c=h=0

    // elementwise state: thread tid<100 owns unit j=tid of BOTH rows
    float c0 = 0.f, c1 = 0.f, h0 = 0.f, h1 = 0.f;

    const float* prep0 = g_pre + ((size_t)(r0 + 0) * TT) * G4 + q;
    const float* prep1 = g_pre + ((size_t)(r0 + 1) * TT) * G4 + q;
    bool is_tanh_gate = (q >= 200 && q < 300);

    // depth-1 prefetch (one full step of latency cover)
    float pf0 = __ldg(prep0); prep0 += G4;
    float pf1 = __ldg(prep1); prep1 += G4;

    const ulonglong2* hp0 = (const ulonglong2*)&h_sh[0][half * 52];
    const ulonglong2* hp1 = (const ulonglong2*)&h_sh[1][half * 52];

    __syncthreads();

    for (int t = 0; t < TT; t++) {
        // ---------- interval A: matvec row0 | update row1 ----------
        {
            float pc = pf0;
            pf0 = __ldg(prep0); prep0 += G4;      // prefetch step t+1 (pad-safe)

            unsigned long long ax = 0ULL, ay = 0ULL;
#pragma unroll
            for (int j = 0; j < 13; j++) {
                ulonglong2 hv = hp0[j];
                ax = fma2(hv.x, Wp[2 * j], ax);
                ay = fma2(hv.y, Wp[2 * j + 1], ay);
            }
            float2 ux = unpack2(ax), uy = unpack2(ay);
            float s = (ux.x + ux.y) + (uy.x + uy.y);
            s += __shfl_xor_sync(0xFFFFFFFFu, s, 1);
            float v = s + pc;
            float act = is_tanh_gate ? tanh_hw(v) : sig_hw(v);
            if (half == 0) gact[0][q] = act;

            if (tid < 100) {   // row-1 elementwise (gates from previous B)
                float iv = gact[1][tid];
                float fv = gact[1][tid + 100];
                float gv = gact[1][tid + 200];
                float ov = gact[1][tid + 300];
                c1 = fv * c1 + iv * gv;
                h1 = ov * tanh_hw(c1);
                h_sh[1][tid] = h1;
            }
        }
        __syncthreads();
        // ---------- interval B: matvec row1 | update row0 ----------
        {
            float pc = pf1;
            pf1 = __ldg(prep1); prep1 += G4;

            unsigned long long ax = 0ULL, ay = 0ULL;
#pragma unroll
            for (int j = 0; j < 13; j++) {
                ulonglong2 hv = hp1[j];
                ax = fma2(hv.x, Wp[2 * j], ax);
                ay = fma2(hv.y, Wp[2 * j + 1], ay);
            }
            float2 ux = unpack2(ax), uy = unpack2(ay);
            float s = (ux.x + ux.y) + (uy.x + uy.y);
            s += __shfl_xor_sync(0xFFFFFFFFu, s, 1);
            float v = s + pc;
            float act = is_tanh_gate ? tanh_hw(v) : sig_hw(v);
            if (half == 0) gact[1][q] = act;

            if (tid < 100) {   // row-0 elementwise (gates from this step's A)
                float iv = gact[0][tid];
                float fv = gact[0][tid + 100];
                float gv = gact[0][tid + 200];
                float ov = gact[0][tid + 300];
                c0 = fv * c0 + iv * gv;
                h0 = ov * tanh_hw(c0);
                h_sh[0][tid] = h0;
            }
        }
        __syncthreads();
    }

    // epilogue: row1's final (step 511) update from the last B's gates
    if (tid < 100) {
        float iv = gact[1][tid];
        float fv = gact[1][tid + 100];
        float gv = gact[1][tid + 200];
        float ov = gact[1][tid + 300];
        c1 = fv * c1 + iv * gv;
        h1 = ov * tanhf_(c1);
        g_hfinal[(r0 + 0) * HID + tid] = h0;
        g_hfinal[(r0 + 1) * HID + tid] = h1;
    }
}

// ================= K3: head  logits = (h@Wo^T + bo)@Wc^T + bc ====================
__global__ void head_kernel(const float* __restrict__ Wo, const float* __restrict__ bo,
                            const float* __restrict__ Wc, const float* __restrict__ bc,
                            float* __restrict__ out) {
    __shared__ float h[HID];
    __shared__ float emb[64];
    int b = blockIdx.x, tid = threadIdx.x;
    if (tid < HID) h[tid] = g_hfinal[b * HID + tid];
    __syncthreads();
    if (tid < 64) {
        float s = bo[tid];
#pragma unroll 4
        for (int j = 0; j < HID; j++) s += h[j] * Wo[tid * HID + j];
        emb[tid] = s;
    }
    __syncthreads();
    if (tid < 10) {
        float s = bc[tid];
#pragma unroll
        for (int e = 0; e < 64; e++) s += emb[e] * Wc[tid * 64 + e];
        out[b * 10 + tid] = s;
    }
}

// ================= launch ========================================================
extern "C" void kernel_launch(void* const* d_in, const int* in_sizes, int n_in,
                              void* d_out, int out_size) {
    const float* x    = (const float*)d_in[0];
    const float* Wih0 = (const float*)d_in[1];
    const float* Whh0 = (const float*)d_in[2];
    const float* bih0 = (const float*)d_in[3];
    const float* bhh0 = (const float*)d_in[4];
    const float* Wo = (const float*)d_in[13];
    const float* bo = (const float*)d_in[14];
    const float* Wc = (const float*)d_in[15];
    const float* bc = (const float*)d_in[16];
    float* out = (float*)d_out;

    prep_kernel<<<200, 256>>>(Wih0, bih0, bhh0);
    gemm_pre_kernel<<<dim3(MTOT / 64, 4), 416>>>(x);
    lstm_kernel<<<128, 800>>>(Whh0);
    head_kernel<<<BB, 128>>>(Wo, bo, Wc, bc, out);
}

// round 13
// speedup vs baseline: 1.2243x; 1.2243x over previous
#include <cuda_runtime.h>
#include <cuda_bf16.h>
#include <cstdint>

// Problem constants
#define BB   256
#define TT   512
#define IND  128
#define HID  100
#define G4   400          // 4*HID
#define MTOT (BB*TT)      // 131072

// ---------------- device scratch (static globals; no runtime alloc) -------------
__device__ float g_WihT[IND * G4];          // [k][g]
__device__ float g_bias[G4];                // bih + bhh
__device__ float g_pre[(MTOT + 2) * G4];    // [m][g] input projection (+2 rows pad)
__device__ float g_hfinal[BB * HID];        // layer-0 final hidden state

// ---------------- f32x2 packed helpers (Blackwell) ------------------------------
__device__ __forceinline__ unsigned long long fma2(unsigned long long a,
                                                   unsigned long long b,
                                                   unsigned long long c) {
    unsigned long long d;
    asm("fma.rn.f32x2 %0, %1, %2, %3;" : "=l"(d) : "l"(a), "l"(b), "l"(c));
    return d;
}
__device__ __forceinline__ unsigned long long pack2(float lo, float hi) {
    unsigned long long d;
    asm("mov.b64 %0, {%1, %2};" : "=l"(d) : "f"(lo), "f"(hi));
    return d;
}
__device__ __forceinline__ float2 unpack2(unsigned long long v) {
    float lo, hi;
    asm("mov.b64 {%0, %1}, %2;" : "=f"(lo), "=f"(hi) : "l"(v));
    return make_float2(lo, hi);
}

// ---------------- hardware tanh activations (sm_75+) -----------------------------
__device__ __forceinline__ float tanh_hw(float x) {
    float y;
    asm("tanh.approx.f32 %0, %1;" : "=f"(y) : "f"(x));
    return y;
}
__device__ __forceinline__ float sig_hw(float x) {
    return fmaf(tanh_hw(0.5f * x), 0.5f, 0.5f);
}

// ---------------- cp.async helpers ------------------------------------------------
__device__ __forceinline__ void cp_async16(void* smem_dst, const void* gmem_src) {
    uint32_t s = (uint32_t)__cvta_generic_to_shared(smem_dst);
    asm volatile("cp.async.ca.shared.global [%0], [%1], 16;" :: "r"(s), "l"(gmem_src));
}
__device__ __forceinline__ void cp_commit() {
    asm volatile("cp.async.commit_group;");
}
__device__ __forceinline__ void cp_wait0() {
    asm volatile("cp.async.wait_group 0;");
}

// ================= K-prep: WihT + fused bias =====================================
__global__ void prep_kernel(const float* __restrict__ Wih,
                            const float* __restrict__ bih,
                            const float* __restrict__ bhh) {
    int idx = blockIdx.x * 256 + threadIdx.x;
    if (idx < G4 * IND) {
        int g = idx / IND, k = idx - g * IND;
        g_WihT[k * G4 + g] = Wih[idx];
    }
    if (idx < G4) g_bias[idx] = bih[idx] + bhh[idx];
}

// ================= K1: pre = x @ WihT + bias — 4-stage cp.async pipeline =========
// Block tile M=64 x N=100; K in four 32-deep stages, double-buffered smem.
// W tiles: 16B cp.async (coalesced, no LDG->STS scoreboard block).
// x tiles: LDG float4 into regs during previous stage's compute, STS after.
__global__ void __launch_bounds__(416, 2) gemm_pre_kernel(const float* __restrict__ x) {
    __shared__ __align__(16) float xs[2][32 * 68];    // [k][m], 8.7KB x2
    __shared__ __align__(16) float ws[2][32 * 108];   // [k][g], 13.8KB x2

    int tid = threadIdx.x;
    int m0 = blockIdx.x * 64;
    int g0 = blockIdx.y * 100;
    int ty = tid & 15;
    int tx = tid >> 4;

    // W staging shares: 32k x 25 gate-quads = 800 16B chunks, 2 per thread
    int wi1 = tid + 416;                      // < 800 guard below
    int wk0 = tid / 25, wg0 = tid - 25 * wk0;
    int wk1 = wi1 / 25, wg1 = wi1 - 25 * wk1;
    // x staging shares: 64m x 8 k-quads = 512 float4, 1-2 per thread
    int xr0 = tid >> 3, xc0 = tid & 7;
    int xr1 = (tid + 416) >> 3, xc1 = (tid + 416) & 7;   // only tid<96

    unsigned long long acc[4][2];
#pragma unroll
    for (int r = 0; r < 4; r++) { acc[r][0] = 0ULL; acc[r][1] = 0ULL; }

    float4 fx0, fx1;

    // ---- prologue: stage 0 ----
    {
        const float* wb = g_WihT + (size_t)0 * G4 + g0;
        cp_async16(&ws[0][wk0 * 108 + 4 * wg0], wb + (size_t)wk0 * G4 + 4 * wg0);
        if (wi1 < 800)
            cp_async16(&ws[0][wk1 * 108 + 4 * wg1], wb + (size_t)wk1 * G4 + 4 * wg1);
        cp_commit();
        fx0 = *(const float4*)&x[(size_t)(m0 + xr0) * IND + 4 * xc0];
        if (tid < 96)
            fx1 = *(const float4*)&x[(size_t)(m0 + xr1) * IND + 4 * xc1];
        xs[0][(4 * xc0 + 0) * 68 + xr0] = fx0.x;
        xs[0][(4 * xc0 + 1) * 68 + xr0] = fx0.y;
        xs[0][(4 * xc0 + 2) * 68 + xr0] = fx0.z;
        xs[0][(4 * xc0 + 3) * 68 + xr0] = fx0.w;
        if (tid < 96) {
            xs[0][(4 * xc1 + 0) * 68 + xr1] = fx1.x;
            xs[0][(4 * xc1 + 1) * 68 + xr1] = fx1.y;
            xs[0][(4 * xc1 + 2) * 68 + xr1] = fx1.z;
            xs[0][(4 * xc1 + 3) * 68 + xr1] = fx1.w;
        }
        cp_wait0();
    }
    __syncthreads();

#pragma unroll
    for (int s = 0; s < 4; s++) {
        int b = s & 1;
        // prefetch stage s+1: W via cp.async into other buffer, x into regs
        if (s < 3) {
            const float* wb = g_WihT + (size_t)(32 * (s + 1)) * G4 + g0;
            cp_async16(&ws[b ^ 1][wk0 * 108 + 4 * wg0], wb + (size_t)wk0 * G4 + 4 * wg0);
            if (wi1 < 800)
                cp_async16(&ws[b ^ 1][wk1 * 108 + 4 * wg1], wb + (size_t)wk1 * G4 + 4 * wg1);
            cp_commit();
            fx0 = *(const float4*)&x[(size_t)(m0 + xr0) * IND + 32 * (s + 1) + 4 * xc0];
            if (tid < 96)
                fx1 = *(const float4*)&x[(size_t)(m0 + xr1) * IND + 32 * (s + 1) + 4 * xc1];
        }
        // compute current stage
        if (tx < 25) {
#pragma unroll
            for (int k = 0; k < 32; k++) {
                float4 xv = *(const float4*)&xs[b][k * 68 + 4 * ty];
                ulonglong2 wv = *(const ulonglong2*)&ws[b][k * 108 + 4 * tx];
                unsigned long long d0 = pack2(xv.x, xv.x);
                unsigned long long d1 = pack2(xv.y, xv.y);
                unsigned long long d2 = pack2(xv.z, xv.z);
                unsigned long long d3 = pack2(xv.w, xv.w);
                acc[0][0] = fma2(d0, wv.x, acc[0][0]);
                acc[0][1] = fma2(d0, wv.y, acc[0][1]);
                acc[1][0] = fma2(d1, wv.x, acc[1][0]);
                acc[1][1] = fma2(d1, wv.y, acc[1][1]);
                acc[2][0] = fma2(d2, wv.x, acc[2][0]);
                acc[2][1] = fma2(d2, wv.y, acc[2][1]);
                acc[3][0] = fma2(d3, wv.x, acc[3][0]);
                acc[3][1] = fma2(d3, wv.y, acc[3][1]);
            }
        }
        // park prefetched x into the other buffer (LDG long since landed)
        if (s < 3) {
            xs[b ^ 1][(4 * xc0 + 0) * 68 + xr0] = fx0.x;
            xs[b ^ 1][(4 * xc0 + 1) * 68 + xr0] = fx0.y;
            xs[b ^ 1][(4 * xc0 + 2) * 68 + xr0] = fx0.z;
            xs[b ^ 1][(4 * xc0 + 3) * 68 + xr0] = fx0.w;
            if (tid < 96) {
                xs[b ^ 1][(4 * xc1 + 0) * 68 + xr1] = fx1.x;
                xs[b ^ 1][(4 * xc1 + 1) * 68 + xr1] = fx1.y;
                xs[b ^ 1][(4 * xc1 + 2) * 68 + xr1] = fx1.z;
                xs[b ^ 1][(4 * xc1 + 3) * 68 + xr1] = fx1.w;
            }
        }
        cp_wait0();
        __syncthreads();
    }

    if (tx < 25) {
        float b0 = g_bias[g0 + 4 * tx + 0];
        float b1 = g_bias[g0 + 4 * tx + 1];
        float b2 = g_bias[g0 + 4 * tx + 2];
        float b3 = g_bias[g0 + 4 * tx + 3];
#pragma unroll
        for (int r = 0; r < 4; r++) {
            float2 e0 = unpack2(acc[r][0]);
            float2 e1 = unpack2(acc[r][1]);
            float4 o = make_float4(e0.x + b0, e0.y + b1, e1.x + b2, e1.y + b3);
            *(float4*)&g_pre[(size_t)(m0 + 4 * ty + r) * G4 + g0 + 4 * tx] = o;
        }
    }
}

// ================= K2: LSTM recurrence — split-K (r7 structure, hw tanh) =========
// 128 blocks x 2 batch rows. Thread = (gate q = tid>>1, k-half = tid&1); Whh
// half-row in 26 packed regs; 4 independent 13-deep fma2 chains per step;
// halves combine via shfl_xor with the adjacent lane. Fastest measured
// structure (r7); activations via hardware tanh.approx.f32 (r10: rel_err 2.5e-6).
__global__ void __launch_bounds__(800, 1) lstm_kernel(const float* __restrict__ Whh) {
    __shared__ float h_sh[2][112];     // [100..112) stay 0 -> zero-padded k-slice
    __shared__ float gact[2][G4];

    int tid = threadIdx.x;
    int bid = blockIdx.x;
    int r0 = bid * 2;
    int q = tid >> 1;          // gate index 0..399
    int half = tid & 1;        // k-half: [0,52) or [52,104)

    unsigned long long Wp[26];
#pragma unroll
    for (int j = 0; j < 26; j++) {
        int k = half * 52 + 2 * j;
        float lo = (k < HID)     ? Whh[q * HID + k]     : 0.f;
        float hi = (k + 1 < HID) ? Whh[q * HID + k + 1] : 0.f;
        Wp[j] = pack2(lo, hi);
    }
    if (tid < 224) ((float*)h_sh)[tid] = 0.f;

    // phase-2 state: thread tid<200 owns (row pr, unit pj)
    float c = 0.f, hloc = 0.f;
    int pr = tid / 100;
    int pj = tid - pr * 100;

    const float* prep = g_pre + ((size_t)(r0 + half) * TT) * G4 + q;
    bool is_tanh_gate = (q >= 200 && q < 300);

    // depth-2 prefetch ring
    float pfa = __ldg(prep); prep += G4;
    float pfb = __ldg(prep); prep += G4;

    __syncthreads();

#pragma unroll 2
    for (int t = 0; t < TT; t++) {
        float pc;
        if ((t & 1) == 0) { pc = pfa; pfa = __ldg(prep); }
        else              { pc = pfb; pfb = __ldg(prep); }
        prep += G4;

        // 4 independent 13-deep chains
        unsigned long long a0x = 0ULL, a0y = 0ULL, a1x = 0ULL, a1y = 0ULL;
        const ulonglong2* hp0 = (const ulonglong2*)&h_sh[0][half * 52];
        const ulonglong2* hp1 = (const ulonglong2*)&h_sh[1][half * 52];
#pragma unroll
        for (int j = 0; j < 13; j++) {
            ulonglong2 hv0 = hp0[j];
            ulonglong2 hv1 = hp1[j];
            a0x = fma2(hv0.x, Wp[2 * j], a0x);
            a0y = fma2(hv0.y, Wp[2 * j + 1], a0y);
            a1x = fma2(hv1.x, Wp[2 * j], a1x);
            a1y = fma2(hv1.y, Wp[2 * j + 1], a1y);
        }
        float2 u0x = unpack2(a0x), u0y = unpack2(a0y);
        float2 u1x = unpack2(a1x), u1y = unpack2(a1y);
        float s0 = (u0x.x + u0x.y) + (u0y.x + u0y.y);
        float s1 = (u1x.x + u1x.y) + (u1y.x + u1y.y);
        s0 += __shfl_xor_sync(0xFFFFFFFFu, s0, 1);
        s1 += __shfl_xor_sync(0xFFFFFFFFu, s1, 1);
        float v = (half ? s1 : s0) + pc;
        gact[half][q] = is_tanh_gate ? tanh_hw(v) : sig_hw(v);

        __syncthreads();
        if (tid < 200) {
            float iv = gact[pr][pj];
            float fv = gact[pr][pj + 100];
            float gv = gact[pr][pj + 200];
            float ov = gact[pr][pj + 300];
            c = fv * c + iv * gv;
            hloc = ov * tanh_hw(c);
            h_sh[pr][pj] = hloc;
        }
        __syncthreads();
    }

    if (tid < 200) g_hfinal[(r0 + pr) * HID + pj] = hloc;
}

// ================= K3: head  logits = (h@Wo^T + bo)@Wc^T + bc ====================
__global__ void head_kernel(const float* __restrict__ Wo, const float* __restrict__ bo,
                            const float* __restrict__ Wc, const float* __restrict__ bc,
                            float* __restrict__ out) {
    __shared__ float h[HID];
    __shared__ float emb[64];
    int b = blockIdx.x, tid = threadIdx.x;
    if (tid < HID) h[tid] = g_hfinal[b * HID + tid];
    __syncthreads();
    if (tid < 64) {
        float s = bo[tid];
#pragma unroll 4
        for (int j = 0; j < HID; j++) s += h[j] * Wo[tid * HID + j];
        emb[tid] = s;
    }
    __syncthreads();
    if (tid < 10) {
        float s = bc[tid];
#pragma unroll
        for (int e = 0; e < 64; e++) s += emb[e] * Wc[tid * 64 + e];
        out[b * 10 + tid] = s;
    }
}

// ================= launch ========================================================
extern "C" void kernel_launch(void* const* d_in, const int* in_sizes, int n_in,
                              void* d_out, int out_size) {
    const float* x    = (const float*)d_in[0];
    const float* Wih0 = (const float*)d_in[1];
    const float* Whh0 = (const float*)d_in[2];
    const float* bih0 = (const float*)d_in[3];
    const float* bhh0 = (const float*)d_in[4];
    const float* Wo = (const float*)d_in[13];
    const float* bo = (const float*)d_in[14];
    const float* Wc = (const float*)d_in[15];
    const float* bc = (const float*)d_in[16];
    float* out = (float*)d_out;

    prep_kernel<<<200, 256>>>(Wih0, bih0, bhh0);
    gemm_pre_kernel<<<dim3(MTOT / 64, 4), 416>>>(x);
    lstm_kernel<<<128, 800>>>(Whh0);
    head_kernel<<<BB, 128>>>(Wo, bo, Wc, bc, out);
}

// round 15
// speedup vs baseline: 1.2290x; 1.0039x over previous
#include <cuda_runtime.h>
#include <cuda_bf16.h>
#include <cstdint>

// Problem constants
#define BB   256
#define TT   512
#define IND  128
#define HID  100
#define G4   400          // 4*HID
#define MTOT (BB*TT)      // 131072

// ---------------- device scratch (static globals; no runtime alloc) -------------
__device__ float g_WihT[IND * G4];          // [k][g]
__device__ float g_bias[G4];                // bih + bhh
__device__ float g_pre[(MTOT + 2) * G4];    // [m][g] input projection (+2 rows pad)
__device__ float g_hfinal[BB * HID];        // layer-0 final hidden state

// ---------------- f32x2 packed helpers (Blackwell) ------------------------------
__device__ __forceinline__ unsigned long long fma2(unsigned long long a,
                                                   unsigned long long b,
                                                   unsigned long long c) {
    unsigned long long d;
    asm("fma.rn.f32x2 %0, %1, %2, %3;" : "=l"(d) : "l"(a), "l"(b), "l"(c));
    return d;
}
__device__ __forceinline__ unsigned long long pack2(float lo, float hi) {
    unsigned long long d;
    asm("mov.b64 %0, {%1, %2};" : "=l"(d) : "f"(lo), "f"(hi));
    return d;
}
__device__ __forceinline__ float2 unpack2(unsigned long long v) {
    float lo, hi;
    asm("mov.b64 {%0, %1}, %2;" : "=f"(lo), "=f"(hi) : "l"(v));
    return make_float2(lo, hi);
}

// ---------------- hardware tanh activations (sm_75+) -----------------------------
__device__ __forceinline__ float tanh_hw(float x) {
    float y;
    asm("tanh.approx.f32 %0, %1;" : "=f"(y) : "f"(x));
    return y;
}
__device__ __forceinline__ float sig_hw(float x) {
    return fmaf(tanh_hw(0.5f * x), 0.5f, 0.5f);
}

// ---------------- cp.async helpers ------------------------------------------------
__device__ __forceinline__ void cp_async16(void* smem_dst, const void* gmem_src) {
    uint32_t s = (uint32_t)__cvta_generic_to_shared(smem_dst);
    asm volatile("cp.async.ca.shared.global [%0], [%1], 16;" :: "r"(s), "l"(gmem_src));
}
__device__ __forceinline__ void cp_commit() {
    asm volatile("cp.async.commit_group;");
}
__device__ __forceinline__ void cp_wait0() {
    asm volatile("cp.async.wait_group 0;");
}

// ================= K-prep: WihT + fused bias =====================================
__global__ void prep_kernel(const float* __restrict__ Wih,
                            const float* __restrict__ bih,
                            const float* __restrict__ bhh) {
    int idx = blockIdx.x * 256 + threadIdx.x;
    if (idx < G4 * IND) {
        int g = idx / IND, k = idx - g * IND;
        g_WihT[k * G4 + g] = Wih[idx];
    }
    if (idx < G4) g_bias[idx] = bih[idx] + bhh[idx];
}

// ================= K1: pre = x @ WihT + bias — 4-stage cp.async pipeline =========
// (byte-identical to the r13-passing version)
__global__ void __launch_bounds__(416, 2) gemm_pre_kernel(const float* __restrict__ x) {
    __shared__ __align__(16) float xs[2][32 * 68];    // [k][m]
    __shared__ __align__(16) float ws[2][32 * 108];   // [k][g]

    int tid = threadIdx.x;
    int m0 = blockIdx.x * 64;
    int g0 = blockIdx.y * 100;
    int ty = tid & 15;
    int tx = tid >> 4;

    int wi1 = tid + 416;
    int wk0 = tid / 25, wg0 = tid - 25 * wk0;
    int wk1 = wi1 / 25, wg1 = wi1 - 25 * wk1;
    int xr0 = tid >> 3, xc0 = tid & 7;
    int xr1 = (tid + 416) >> 3, xc1 = (tid + 416) & 7;

    unsigned long long acc[4][2];
#pragma unroll
    for (int r = 0; r < 4; r++) { acc[r][0] = 0ULL; acc[r][1] = 0ULL; }

    float4 fx0, fx1;

    {
        const float* wb = g_WihT + (size_t)0 * G4 + g0;
        cp_async16(&ws[0][wk0 * 108 + 4 * wg0], wb + (size_t)wk0 * G4 + 4 * wg0);
        if (wi1 < 800)
            cp_async16(&ws[0][wk1 * 108 + 4 * wg1], wb + (size_t)wk1 * G4 + 4 * wg1);
        cp_commit();
        fx0 = *(const float4*)&x[(size_t)(m0 + xr0) * IND + 4 * xc0];
        if (tid < 96)
            fx1 = *(const float4*)&x[(size_t)(m0 + xr1) * IND + 4 * xc1];
        xs[0][(4 * xc0 + 0) * 68 + xr0] = fx0.x;
        xs[0][(4 * xc0 + 1) * 68 + xr0] = fx0.y;
        xs[0][(4 * xc0 + 2) * 68 + xr0] = fx0.z;
        xs[0][(4 * xc0 + 3) * 68 + xr0] = fx0.w;
        if (tid < 96) {
            xs[0][(4 * xc1 + 0) * 68 + xr1] = fx1.x;
            xs[0][(4 * xc1 + 1) * 68 + xr1] = fx1.y;
            xs[0][(4 * xc1 + 2) * 68 + xr1] = fx1.z;
            xs[0][(4 * xc1 + 3) * 68 + xr1] = fx1.w;
        }
        cp_wait0();
    }
    __syncthreads();

#pragma unroll
    for (int s = 0; s < 4; s++) {
        int b = s & 1;
        if (s < 3) {
            const float* wb = g_WihT + (size_t)(32 * (s + 1)) * G4 + g0;
            cp_async16(&ws[b ^ 1][wk0 * 108 + 4 * wg0], wb + (size_t)wk0 * G4 + 4 * wg0);
            if (wi1 < 800)
                cp_async16(&ws[b ^ 1][wk1 * 108 + 4 * wg1], wb + (size_t)wk1 * G4 + 4 * wg1);
            cp_commit();
            fx0 = *(const float4*)&x[(size_t)(m0 + xr0) * IND + 32 * (s + 1) + 4 * xc0];
            if (tid < 96)
                fx1 = *(const float4*)&x[(size_t)(m0 + xr1) * IND + 32 * (s + 1) + 4 * xc1];
        }
        if (tx < 25) {
#pragma unroll
            for (int k = 0; k < 32; k++) {
                float4 xv = *(const float4*)&xs[b][k * 68 + 4 * ty];
                ulonglong2 wv = *(const ulonglong2*)&ws[b][k * 108 + 4 * tx];
                unsigned long long d0 = pack2(xv.x, xv.x);
                unsigned long long d1 = pack2(xv.y, xv.y);
                unsigned long long d2 = pack2(xv.z, xv.z);
                unsigned long long d3 = pack2(xv.w, xv.w);
                acc[0][0] = fma2(d0, wv.x, acc[0][0]);
                acc[0][1] = fma2(d0, wv.y, acc[0][1]);
                acc[1][0] = fma2(d1, wv.x, acc[1][0]);
                acc[1][1] = fma2(d1, wv.y, acc[1][1]);
                acc[2][0] = fma2(d2, wv.x, acc[2][0]);
                acc[2][1] = fma2(d2, wv.y, acc[2][1]);
                acc[3][0] = fma2(d3, wv.x, acc[3][0]);
                acc[3][1] = fma2(d3, wv.y, acc[3][1]);
            }
        }
        if (s < 3) {
            xs[b ^ 1][(4 * xc0 + 0) * 68 + xr0] = fx0.x;
            xs[b ^ 1][(4 * xc0 + 1) * 68 + xr0] = fx0.y;
            xs[b ^ 1][(4 * xc0 + 2) * 68 + xr0] = fx0.z;
            xs[b ^ 1][(4 * xc0 + 3) * 68 + xr0] = fx0.w;
            if (tid < 96) {
                xs[b ^ 1][(4 * xc1 + 0) * 68 + xr1] = fx1.x;
                xs[b ^ 1][(4 * xc1 + 1) * 68 + xr1] = fx1.y;
                xs[b ^ 1][(4 * xc1 + 2) * 68 + xr1] = fx1.z;
                xs[b ^ 1][(4 * xc1 + 3) * 68 + xr1] = fx1.w;
            }
        }
        cp_wait0();
        __syncthreads();
    }

    if (tx < 25) {
        float b0 = g_bias[g0 + 4 * tx + 0];
        float b1 = g_bias[g0 + 4 * tx + 1];
        float b2 = g_bias[g0 + 4 * tx + 2];
        float b3 = g_bias[g0 + 4 * tx + 3];
#pragma unroll
        for (int r = 0; r < 4; r++) {
            float2 e0 = unpack2(acc[r][0]);
            float2 e1 = unpack2(acc[r][1]);
            float4 o = make_float4(e0.x + b0, e0.y + b1, e1.x + b2, e1.y + b3);
            *(float4*)&g_pre[(size_t)(m0 + 4 * ty + r) * G4 + g0 + 4 * tx] = o;
        }
    }
}

// ================= K2: LSTM recurrence — split-K, register diet ==================
// Changes vs r13-passing version (spill-elimination theory):
//   * accumulators 4 -> 2 (one per row; 26-deep chains covered by 6.25 w/SMSP)
//   * prefetch ring depth 2 -> 1 (still ~1 full step of DRAM-latency cover)
//   * no t-loop unroll (no ring parity needed)
//   * phase-2 moved to TOP warps (tid>=600): hi-wid-first arbiter priority
// Estimated live regs ~75 < 81 cap at 800 threads -> no hot-loop LDL/STL.
__global__ void __launch_bounds__(800, 1) lstm_kernel(const float* __restrict__ Whh) {
    __shared__ float h_sh[2][112];     // [100..112) stay 0 -> zero-padded k-slice
    __shared__ float gact[2][G4];

    int tid = threadIdx.x;
    int r0 = blockIdx.x * 2;
    int q = tid >> 1;          // gate index 0..399
    int half = tid & 1;        // k-half: [0,52) or [52,104)

    unsigned long long Wp[26];
#pragma unroll
    for (int j = 0; j < 26; j++) {
        int k = half * 52 + 2 * j;
        float lo = (k < HID)     ? Whh[q * HID + k]     : 0.f;
        float hi = (k + 1 < HID) ? Whh[q * HID + k + 1] : 0.f;
        Wp[j] = pack2(lo, hi);
    }
    if (tid < 224) ((float*)h_sh)[tid] = 0.f;

    float c = 0.f, hloc = 0.f;

    const float* prep = g_pre + ((size_t)(r0 + half) * TT) * G4 + q;
    bool is_tanh_gate = (q >= 200 && q < 300);

    // depth-1 prefetch (one full step of latency cover; pad rows keep tail safe)
    float pf = __ldg(prep); prep += G4;

    const ulonglong2* hp0 = (const ulonglong2*)&h_sh[0][half * 52];
    const ulonglong2* hp1 = (const ulonglong2*)&h_sh[1][half * 52];

    __syncthreads();

    for (int t = 0; t < TT; t++) {
        float pc = pf;
        pf = __ldg(prep); prep += G4;

        unsigned long long a0 = 0ULL, a1 = 0ULL;
#pragma unroll
        for (int j = 0; j < 13; j++) {
            ulonglong2 hv0 = hp0[j];
            ulonglong2 hv1 = hp1[j];
            a0 = fma2(hv0.x, Wp[2 * j], a0);
            a0 = fma2(hv0.y, Wp[2 * j + 1], a0);
            a1 = fma2(hv1.x, Wp[2 * j], a1);
            a1 = fma2(hv1.y, Wp[2 * j + 1], a1);
        }
        float2 u0 = unpack2(a0);
        float2 u1 = unpack2(a1);
        float s0 = u0.x + u0.y;
        float s1 = u1.x + u1.y;
        s0 += __shfl_xor_sync(0xFFFFFFFFu, s0, 1);
        s1 += __shfl_xor_sync(0xFFFFFFFFu, s1, 1);
        float v = (half ? s1 : s0) + pc;
        gact[half][q] = is_tanh_gate ? tanh_hw(v) : sig_hw(v);

        __syncthreads();
        if (tid >= 600) {          // top 200 threads: warps 18.75..25 (hi priority)
            int i2 = tid - 600;
            int pr = i2 / 100;
            int pj = i2 - pr * 100;
            float iv = gact[pr][pj];
            float fv = gact[pr][pj + 100];
            float gv = gact[pr][pj + 200];
            float ov = gact[pr][pj + 300];
            c = fv * c + iv * gv;
            hloc = ov * tanh_hw(c);
            h_sh[pr][pj] = hloc;
        }
        __syncthreads();
    }

    if (tid >= 600) {
        int i2 = tid - 600;
        int pr = i2 / 100;
        int pj = i2 - pr * 100;
        g_hfinal[(r0 + pr) * HID + pj] = hloc;
    }
}

// ================= K3: head  logits = (h@Wo^T + bo)@Wc^T + bc ====================
__global__ void head_kernel(const float* __restrict__ Wo, const float* __restrict__ bo,
                            const float* __restrict__ Wc, const float* __restrict__ bc,
                            float* __restrict__ out) {
    __shared__ float h[HID];
    __shared__ float emb[64];
    int b = blockIdx.x, tid = threadIdx.x;
    if (tid < HID) h[tid] = g_hfinal[b * HID + tid];
    __syncthreads();
    if (tid < 64) {
        float s = bo[tid];
#pragma unroll 4
        for (int j = 0; j < HID; j++) s += h[j] * Wo[tid * HID + j];
        emb[tid] = s;
    }
    __syncthreads();
    if (tid < 10) {
        float s = bc[tid];
#pragma unroll
        for (int e = 0; e < 64; e++) s += emb[e] * Wc[tid * 64 + e];
        out[b * 10 + tid] = s;
    }
}

// ================= launch ========================================================
extern "C" void kernel_launch(void* const* d_in, const int* in_sizes, int n_in,
                              void* d_out, int out_size) {
    const float* x    = (const float*)d_in[0];
    const float* Wih0 = (const float*)d_in[1];
    const float* Whh0 = (const float*)d_in[2];
    const float* bih0 = (const float*)d_in[3];
    const float* bhh0 = (const float*)d_in[4];
    const float* Wo = (const float*)d_in[13];
    const float* bo = (const float*)d_in[14];
    const float* Wc = (const float*)d_in[15];
    const float* bc = (const float*)d_in[16];
    float* out = (float*)d_out;

    prep_kernel<<<200, 256>>>(Wih0, bih0, bhh0);
    gemm_pre_kernel<<<dim3(MTOT / 64, 4), 416>>>(x);
    lstm_kernel<<<128, 800>>>(Whh0);
    head_kernel<<<BB, 128>>>(Wo, bo, Wc, bc, out);
}